// round 2
// baseline (speedup 1.0000x reference)
#include <cuda_runtime.h>
#include <math.h>

// Problem constants
#define Bn   8
#define Cin  128
#define Cout 128
#define Hn   112
#define Wn   112
#define Kk   9
#define HW   (Hn*Wn)            // 12544
#define NPIX (Bn*HW)            // 100352
#define KDIM (Cin*Kk)           // 1152

// ---------------- device scratch (no runtime alloc allowed) ----------------
__device__ float4 g_wT4[KDIM*32];            // [kk][o/4] : w transposed, 590KB
__device__ float  g_owT[KDIM*28];            // offset+mask weights, [kk][m(28, padded)]
__device__ float4 g_meta_w[NPIX*Kk];         // bilinear tap weights (mask folded)
__device__ int4   g_meta_off[NPIX*Kk];       // clamped plane offsets y*W+x

// ---------------- kernel 0: weight repack ----------------
__global__ void prep_weights_kernel(const float* __restrict__ w,
                                    const float* __restrict__ ow,
                                    const float* __restrict__ mw) {
    int idx = blockIdx.x * 256 + threadIdx.x;
    if (idx < KDIM * 128) {
        int kk = idx >> 7, o = idx & 127;
        ((float*)g_wT4)[idx] = w[o * KDIM + kk];
    }
    if (idx < KDIM * 28) {
        int kk = idx / 28, m = idx - (idx / 28) * 28;
        float v = 0.f;
        if (m < 18)      v = ow[m * KDIM + kk];
        else if (m < 27) v = mw[(m - 18) * KDIM + kk];
        g_owT[idx] = v;
    }
}

// ---------------- kernel 1: offset/mask conv -> sampling metadata ----------------
__global__ void __launch_bounds__(128)
offmask_kernel(const float* __restrict__ x,
               const float* __restrict__ ob,
               const float* __restrict__ mb) {
    __shared__ float s_w[16 * 9 * 28];   // 4032 floats = 16KB
    const int tid = threadIdx.x;
    const int pix = blockIdx.x * 128 + tid;
    const int b = pix / HW;
    const int rem = pix - b * HW;
    const int h = rem / Wn;
    const int wc = rem - h * Wn;
    const float* xb = x + (size_t)b * Cin * HW;

    float a[28];
#pragma unroll
    for (int m = 0; m < 28; m++)
        a[m] = (m < 18) ? __ldg(ob + m) : ((m < 27) ? __ldg(mb + m - 18) : 0.f);

    for (int c0 = 0; c0 < Cin; c0 += 16) {
        __syncthreads();
        for (int i = tid; i < 4032; i += 128) s_w[i] = g_owT[c0 * 252 + i];
        __syncthreads();
#pragma unroll 4
        for (int cc = 0; cc < 16; ++cc) {
            const float* xc = xb + (c0 + cc) * HW;
            float tap[9];
#pragma unroll
            for (int di = 0; di < 3; di++)
#pragma unroll
                for (int dj = 0; dj < 3; dj++) {
                    int y = h - 1 + di, xx = wc - 1 + dj;
                    bool ok = ((unsigned)y < (unsigned)Hn) && ((unsigned)xx < (unsigned)Wn);
                    tap[di * 3 + dj] = ok ? __ldg(xc + y * Wn + xx) : 0.f;
                }
#pragma unroll
            for (int k = 0; k < 9; k++) {
                float xv = tap[k];
                const float4* wr = (const float4*)&s_w[(cc * 9 + k) * 28];
#pragma unroll
                for (int q = 0; q < 7; q++) {
                    float4 wv = wr[q];
                    a[q * 4 + 0] += xv * wv.x;
                    a[q * 4 + 1] += xv * wv.y;
                    a[q * 4 + 2] += xv * wv.z;
                    a[q * 4 + 3] += xv * wv.w;
                }
            }
        }
    }

    // epilogue: build per-(pixel,k) bilinear metadata
#pragma unroll
    for (int k = 0; k < 9; k++) {
        float dy = a[2 * k], dx = a[2 * k + 1];
        float mraw = a[18 + k];
        float mval = 2.f / (1.f + expf(-mraw));
        int ki = k / 3, kj = k - ki * 3;
        float ys = (float)(h - 1 + ki) + dy;
        float xs = (float)(wc - 1 + kj) + dx;
        float y0f = floorf(ys), x0f = floorf(xs);
        float ly = ys - y0f, lx = xs - x0f;
        int y0 = (int)y0f, x0 = (int)x0f;
        int y1 = y0 + 1, x1 = x0 + 1;
        float vy0 = ((unsigned)y0 < (unsigned)Hn) ? 1.f : 0.f;
        float vy1 = ((unsigned)y1 < (unsigned)Hn) ? 1.f : 0.f;
        float vx0 = ((unsigned)x0 < (unsigned)Wn) ? 1.f : 0.f;
        float vx1 = ((unsigned)x1 < (unsigned)Wn) ? 1.f : 0.f;
        float w00 = mval * (1.f - ly) * (1.f - lx) * vy0 * vx0;
        float w01 = mval * (1.f - ly) * lx          * vy0 * vx1;
        float w10 = mval * ly          * (1.f - lx) * vy1 * vx0;
        float w11 = mval * ly          * lx          * vy1 * vx1;
        int y0c = min(max(y0, 0), Hn - 1), y1c = min(max(y1, 0), Hn - 1);
        int x0c = min(max(x0, 0), Wn - 1), x1c = min(max(x1, 0), Wn - 1);
        int oy0 = y0c * Wn, oy1 = y1c * Wn;
        g_meta_w[pix * 9 + k]   = make_float4(w00, w01, w10, w11);
        g_meta_off[pix * 9 + k] = make_int4(oy0 + x0c, oy0 + x1c, oy1 + x0c, oy1 + x1c);
    }
}

// ---------------- kernel 2: fused bilinear-sample + GEMM ----------------
// Block: 256 threads, 64 pixels x 128 output channels.
// warp id og (0..7): owns 16 consecutive o-channels (og*16..+15)
// lane (0..31): pixels {lane, lane+32}
__global__ void __launch_bounds__(256)
main_kernel(const float* __restrict__ x,
            const float* __restrict__ bias,
            float* __restrict__ out) {
    __shared__ float4 s_mw[576];
    __shared__ int4   s_mo[576];
    __shared__ float  s_s[36 * 64];

    const int tid = threadIdx.x;
    const int pix0 = blockIdx.x * 64;
    const int b = pix0 / HW;
    const int hw0 = pix0 - b * HW;
    const int lane = tid & 31;
    const int og = tid >> 5;
    const int p_s = tid & 63;
    const int kk0 = tid >> 6;

    // load sampling metadata for 64 pixels x 9 taps
    for (int i = tid; i < 576; i += 256) {
        s_mw[i] = g_meta_w[pix0 * 9 + i];
        s_mo[i] = g_meta_off[pix0 * 9 + i];
    }
    __syncthreads();

    const float* xb = x + (size_t)b * Cin * HW;
    float4 a0[4] = {make_float4(0,0,0,0), make_float4(0,0,0,0),
                    make_float4(0,0,0,0), make_float4(0,0,0,0)};
    float4 a1[4] = {make_float4(0,0,0,0), make_float4(0,0,0,0),
                    make_float4(0,0,0,0), make_float4(0,0,0,0)};

    for (int c0 = 0; c0 < Cin; c0 += 4) {
        // ---- cooperative bilinear sampling: s_s[kkl][p], kkl = cc*9+k ----
#pragma unroll
        for (int i = 0; i < 9; ++i) {
            int kkl = kk0 + i * 4;          // 0..35, warp-uniform
            int cc = kkl / 9;
            int k = kkl - cc * 9;
            const float* xc = xb + (c0 + cc) * HW;
            int mi = p_s * 9 + k;
            float4 wv = s_mw[mi];
            int4 ov = s_mo[mi];
            float s = wv.x * __ldg(xc + ov.x) + wv.y * __ldg(xc + ov.y)
                    + wv.z * __ldg(xc + ov.z) + wv.w * __ldg(xc + ov.w);
            s_s[kkl * 64 + p_s] = s;
        }
        __syncthreads();

        // ---- GEMM micro-tile ----
        const float4* wrow = g_wT4 + (c0 * 9) * 32 + og * 4;
#pragma unroll 6
        for (int kkl = 0; kkl < 36; ++kkl) {
            float s0 = s_s[kkl * 64 + lane];
            float s1 = s_s[kkl * 64 + 32 + lane];
            const float4* wr = wrow + kkl * 32;
#pragma unroll
            for (int q = 0; q < 4; ++q) {
                float4 wv = __ldg(wr + q);
                a0[q].x += s0 * wv.x; a0[q].y += s0 * wv.y;
                a0[q].z += s0 * wv.z; a0[q].w += s0 * wv.w;
                a1[q].x += s1 * wv.x; a1[q].y += s1 * wv.y;
                a1[q].z += s1 * wv.z; a1[q].w += s1 * wv.w;
            }
        }
        __syncthreads();
    }

    // ---- epilogue: coalesced stores (lanes span consecutive pixels) ----
    float* ob = out + (size_t)b * Cout * HW + hw0 + lane;
#pragma unroll
    for (int q = 0; q < 4; q++) {
        const float* aa0 = (const float*)&a0[q];
        const float* aa1 = (const float*)&a1[q];
#pragma unroll
        for (int e = 0; e < 4; e++) {
            int o = og * 16 + q * 4 + e;
            float bb = __ldg(bias + o);
            ob[(size_t)o * HW]      = aa0[e] + bb;
            ob[(size_t)o * HW + 32] = aa1[e] + bb;
        }
    }
}

// ---------------- launcher ----------------
extern "C" void kernel_launch(void* const* d_in, const int* in_sizes, int n_in,
                              void* d_out, int out_size) {
    const float* x        = (const float*)d_in[0];
    const float* offset_w = (const float*)d_in[1];
    const float* offset_b = (const float*)d_in[2];
    const float* mod_w    = (const float*)d_in[3];
    const float* mod_b    = (const float*)d_in[4];
    const float* w        = (const float*)d_in[5];
    const float* bias     = (const float*)d_in[6];
    float* out = (float*)d_out;

    prep_weights_kernel<<<(KDIM * 128 + 255) / 256, 256>>>(w, offset_w, mod_w);
    offmask_kernel<<<NPIX / 128, 128>>>(x, offset_b, mod_b);
    main_kernel<<<NPIX / 64, 256>>>(x, bias, out);
}